// round 1
// baseline (speedup 1.0000x reference)
#include <cuda_runtime.h>
#include <math.h>

// ---------------- problem constants ----------------
#define BB   8
#define CC   384
#define HH   48
#define WW   48
#define NN   2304          // HH*WW
#define NHH  12
#define NPP  4
#define HDD  32
#define SCALE_F 0.17677669529663687f   // 1/sqrt(32)

// ---------------- scratch (no allocations allowed) ----------------
__device__ float g_q    [BB*CC*NN];
__device__ float g_cg   [BB*CC*NN];
__device__ float g_k    [BB*CC*NN];
__device__ float g_v    [BB*CC*NN];
__device__ float g_dw   [BB*CC*NN];
__device__ float g_ao   [BB*CC*NN];
__device__ float g_pool [BB*CC*49];
__device__ float g_gs   [BB*32*49];
__device__ float g_guide[BB*32*NN];
__device__ float g_off  [BB*NN*96];

__device__ __forceinline__ float gelu_f(float x) {
    return 0.5f * x * (1.0f + erff(x * 0.7071067811865476f));
}

// ---------------- tiled SGEMM: out[b,o,n] = sum_c W[o,c]*in[b,c,n] ----------------
// mode 0: plain, 1: gelu epilogue, 2: batchnorm epilogue
__global__ void gemm384_kernel(const float* __restrict__ Wm,
                               const float* __restrict__ in,
                               float* __restrict__ out,
                               int mode,
                               const float* __restrict__ bng,
                               const float* __restrict__ bnb,
                               const float* __restrict__ bnm,
                               const float* __restrict__ bnv)
{
    __shared__ float As[16][64];
    __shared__ float Bs[16][64];

    const int tid = threadIdx.x;          // 0..255
    const int tx  = tid & 15;
    const int ty  = tid >> 4;
    const int n0  = blockIdx.x * 64;
    const int o0  = blockIdx.y * 64;
    const int b   = blockIdx.z;

    const float* inb = in + (size_t)b * CC * NN;

    float acc[4][4];
#pragma unroll
    for (int i = 0; i < 4; i++)
#pragma unroll
        for (int j = 0; j < 4; j++) acc[i][j] = 0.f;

    for (int kb = 0; kb < CC; kb += 16) {
#pragma unroll
        for (int i = 0; i < 4; i++) {
            int idx = tid + i * 256;
            int col = idx & 63;
            int row = idx >> 6;           // 0..15
            As[row][col] = Wm[(size_t)(o0 + col) * CC + kb + row];
            Bs[row][col] = inb[(size_t)(kb + row) * NN + n0 + col];
        }
        __syncthreads();
#pragma unroll
        for (int kk = 0; kk < 16; kk++) {
            float a[4], bv[4];
#pragma unroll
            for (int i = 0; i < 4; i++) a[i]  = As[kk][ty * 4 + i];
#pragma unroll
            for (int j = 0; j < 4; j++) bv[j] = Bs[kk][tx * 4 + j];
#pragma unroll
            for (int i = 0; i < 4; i++)
#pragma unroll
                for (int j = 0; j < 4; j++) acc[i][j] += a[i] * bv[j];
        }
        __syncthreads();
    }

    float* outb = out + (size_t)b * CC * NN;   // note: for O=384 outputs only
#pragma unroll
    for (int i = 0; i < 4; i++) {
        int o = o0 + ty * 4 + i;
        float gg = 0.f, bb2 = 0.f, mm = 0.f, iv = 1.f;
        if (mode == 2) {
            gg = bng[o]; bb2 = bnb[o]; mm = bnm[o];
            iv = rsqrtf(bnv[o] + 1e-5f);
        }
#pragma unroll
        for (int j = 0; j < 4; j++) {
            int n = n0 + tx * 4 + j;
            float v = acc[i][j];
            if (mode == 1) v = gelu_f(v);
            else if (mode == 2) v = gg * (v - mm) * iv + bb2;
            outb[(size_t)o * NN + n] = v;
        }
    }
}

// ---------------- adaptive avg pool 48x48 -> 7x7 ----------------
__global__ void pool_kernel(const float* __restrict__ in, float* __restrict__ out)
{
    int idx = blockIdx.x * blockDim.x + threadIdx.x;     // b*C*49
    if (idx >= BB * CC * 49) return;
    int p = idx % 7;
    int o = (idx / 7) % 7;
    int c = (idx / 49) % CC;
    int b = idx / (49 * CC);

    int sy = o * HH / 7,       ey = ((o + 1) * HH + 6) / 7;
    int sx = p * WW / 7,       ex = ((p + 1) * WW + 6) / 7;
    const float* f = in + ((size_t)b * CC + c) * NN;
    float s = 0.f;
    for (int y = sy; y < ey; y++)
        for (int x = sx; x < ex; x++)
            s += f[y * WW + x];
    out[idx] = s / (float)((ey - sy) * (ex - sx));
}

// ---------------- LN over channels (pooled) + W_post projection ----------------
__global__ void ln1_post_kernel(const float* __restrict__ pool,
                                const float* __restrict__ g1,
                                const float* __restrict__ b1,
                                const float* __restrict__ Wpost,
                                float* __restrict__ gs)
{
    __shared__ float rs[CC], rq[CC], xn[CC];
    __shared__ float s_mu, s_rstd;
    int t = threadIdx.x;                   // 0..383
    int b = blockIdx.x / 49;
    int s = blockIdx.x % 49;

    float x = pool[((size_t)b * CC + t) * 49 + s];
    rs[t] = x; rq[t] = x * x;
    __syncthreads();
    for (int st = 192; st >= 6; st >>= 1) {
        if (t < st) { rs[t] += rs[t + st]; rq[t] += rq[t + st]; }
        __syncthreads();
    }
    if (t == 0) {
        float a = 0.f, q = 0.f;
        for (int i = 0; i < 6; i++) { a += rs[i]; q += rq[i]; }
        float mu = a / CC;
        float var = q / CC - mu * mu;
        s_mu = mu; s_rstd = rsqrtf(var + 1e-6f);
    }
    __syncthreads();
    xn[t] = (x - s_mu) * s_rstd * g1[t] + b1[t];
    __syncthreads();
    if (t < 32) {
        float acc = 0.f;
        const float* wr = Wpost + (size_t)t * CC;
        for (int c = 0; c < CC; c++) acc += wr[c] * xn[c];
        gs[((size_t)b * 32 + t) * 49 + s] = acc;
    }
}

// ---------------- bilinear upsample 7x7 -> 48x48 ----------------
__global__ void upsample_kernel(const float* __restrict__ gs, float* __restrict__ guide)
{
    int idx = blockIdx.x * blockDim.x + threadIdx.x;
    if (idx >= BB * 32 * NN) return;
    int x = idx % WW;
    int y = (idx / WW) % HH;
    int c = (idx / NN) % 32;
    int b = idx / (NN * 32);

    float sy = (y + 0.5f) * (7.0f / 48.0f) - 0.5f;
    sy = fminf(fmaxf(sy, 0.f), 6.f);
    int i0y = (int)floorf(sy);
    int i1y = min(i0y + 1, 6);
    float fy = sy - (float)i0y;

    float sx = (x + 0.5f) * (7.0f / 48.0f) - 0.5f;
    sx = fminf(fmaxf(sx, 0.f), 6.f);
    int i0x = (int)floorf(sx);
    int i1x = min(i0x + 1, 6);
    float fx = sx - (float)i0x;

    const float* f = gs + ((size_t)b * 32 + c) * 49;
    float v = (1.f - fy) * ((1.f - fx) * f[i0y * 7 + i0x] + fx * f[i0y * 7 + i1x])
            +        fy  * ((1.f - fx) * f[i1y * 7 + i0x] + fx * f[i1y * 7 + i1x]);
    guide[((size_t)b * 32 + c) * NN + y * WW + x] = v;
}

// ---------------- 3x3 depthwise conv + bias ----------------
__global__ void dwconv_kernel(const float* __restrict__ in,
                              const float* __restrict__ w,
                              const float* __restrict__ bias,
                              float* __restrict__ out)
{
    int idx = blockIdx.x * blockDim.x + threadIdx.x;
    if (idx >= BB * CC * NN) return;
    int x = idx % WW;
    int y = (idx / WW) % HH;
    int c = (idx / NN) % CC;
    int b = idx / (NN * CC);

    const float* f  = in + ((size_t)b * CC + c) * NN;
    const float* wc = w + (size_t)c * 9;
    float s = 0.f;
#pragma unroll
    for (int dy = 0; dy < 3; dy++) {
        int yy = y + dy - 1;
        if (yy < 0 || yy >= HH) continue;
#pragma unroll
        for (int dx = 0; dx < 3; dx++) {
            int xx = x + dx - 1;
            if (xx < 0 || xx >= WW) continue;
            s += f[yy * WW + xx] * wc[dy * 3 + dx];
        }
    }
    out[idx] = s + bias[c];
}

// ---------------- per-pixel LN2 + gelu + W_lo + concat(guide) + W_off ----------------
__global__ void offsets_kernel(const float* __restrict__ dw,
                               const float* __restrict__ g2,
                               const float* __restrict__ b2,
                               const float* __restrict__ Wlo,
                               const float* __restrict__ blo,
                               const float* __restrict__ guide,
                               const float* __restrict__ Woff,
                               const float* __restrict__ boff,
                               float* __restrict__ off)
{
    __shared__ float rs[CC], rq[CC], xg[CC];
    __shared__ float fused[64];
    __shared__ float s_mu, s_rstd;
    int t = threadIdx.x;                // 0..383
    int b = blockIdx.x / NN;
    int n = blockIdx.x % NN;

    float x = dw[((size_t)b * CC + t) * NN + n];
    rs[t] = x; rq[t] = x * x;
    __syncthreads();
    for (int st = 192; st >= 6; st >>= 1) {
        if (t < st) { rs[t] += rs[t + st]; rq[t] += rq[t + st]; }
        __syncthreads();
    }
    if (t == 0) {
        float a = 0.f, q = 0.f;
        for (int i = 0; i < 6; i++) { a += rs[i]; q += rq[i]; }
        float mu = a / CC;
        float var = q / CC - mu * mu;
        s_mu = mu; s_rstd = rsqrtf(var + 1e-6f);
    }
    __syncthreads();
    xg[t] = gelu_f((x - s_mu) * s_rstd * g2[t] + b2[t]);
    __syncthreads();

    if (t < 32) {
        float acc = blo[t];
        const float* wr = Wlo + (size_t)t * CC;
        for (int c = 0; c < CC; c++) acc += wr[c] * xg[c];
        fused[32 + t] = acc;                      // lo goes second
    } else if (t < 64) {
        fused[t - 32] = guide[((size_t)b * 32 + (t - 32)) * NN + n];  // guide first
    }
    __syncthreads();

    if (t < 96) {
        float acc = boff[t];
        const float* wr = Woff + (size_t)t * 64;
#pragma unroll
        for (int c = 0; c < 64; c++) acc += wr[c] * fused[c];
        off[((size_t)b * NN + n) * 96 + t] = acc;
    }
}

// ---------------- fused deformable attention: warp per (b,h,n) ----------------
__global__ void attn_kernel(const float* __restrict__ qb,
                            const float* __restrict__ kb,
                            const float* __restrict__ vb,
                            const float* __restrict__ offb,
                            const float* __restrict__ abias,
                            float* __restrict__ outb)
{
    int gw   = (blockIdx.x * blockDim.x + threadIdx.x) >> 5;
    int lane = threadIdx.x & 31;
    if (gw >= BB * NHH * NN) return;
    int n = gw % NN;
    int h = (gw / NN) % NHH;
    int b = gw / (NN * NHH);
    int qx = n % WW;
    int qy = n / WW;

    const float* kf = kb + ((size_t)(b * NHH + h) * HDD + lane) * NN;
    const float* vf = vb + ((size_t)(b * NHH + h) * HDD + lane) * NN;
    float qv = qb[((size_t)(b * NHH + h) * HDD + lane) * NN + n];
    const float* op = offb + ((size_t)b * NN + n) * 96 + h * (NPP * 2);

    float sc[NPP], vs[NPP];
#pragma unroll
    for (int p = 0; p < NPP; p++) {
        float ox = op[p * 2 + 0];
        float oy = op[p * 2 + 1];
        // exact reference arithmetic (matters for rint at .5 boundaries)
        float gx = (((float)qx + 0.5f) / (float)WW + ox / (float)WW) * 2.0f - 1.0f;
        float gy = (((float)qy + 0.5f) / (float)HH + oy / (float)HH) * 2.0f - 1.0f;
        float x = (gx + 1.0f) * 0.5f * (float)WW - 0.5f;
        float y = (gy + 1.0f) * 0.5f * (float)HH - 0.5f;
        float x0f = floorf(x), y0f = floorf(y);
        float fx = x - x0f, fy = y - y0f;
        int x0 = (int)x0f, y0 = (int)y0f;
        int x1 = x0 + 1,  y1 = y0 + 1;
        bool vx0 = (x0 >= 0 && x0 < WW), vx1 = (x1 >= 0 && x1 < WW);
        bool vy0 = (y0 >= 0 && y0 < HH), vy1 = (y1 >= 0 && y1 < HH);
        float w00 = (1.f - fx) * (1.f - fy);
        float w01 = fx * (1.f - fy);
        float w10 = (1.f - fx) * fy;
        float w11 = fx * fy;

        float ks = 0.f, vsmp = 0.f;
        if (vx0 && vy0) { int i = y0 * WW + x0; ks += w00 * kf[i]; vsmp += w00 * vf[i]; }
        if (vx1 && vy0) { int i = y0 * WW + x1; ks += w01 * kf[i]; vsmp += w01 * vf[i]; }
        if (vx0 && vy1) { int i = y1 * WW + x0; ks += w10 * kf[i]; vsmp += w10 * vf[i]; }
        if (vx1 && vy1) { int i = y1 * WW + x1; ks += w11 * kf[i]; vsmp += w11 * vf[i]; }
        vs[p] = vsmp;

        float part = qv * ks;
#pragma unroll
        for (int s = 16; s > 0; s >>= 1)
            part += __shfl_xor_sync(0xffffffffu, part, s);

        int px = (int)rintf(x); px = min(max(px, 0), WW - 1);
        int py = (int)rintf(y); py = min(max(py, 0), HH - 1);
        int bidx = abs(qy - py) * WW + abs(qx - px);
        sc[p] = part * SCALE_F + abias[h * NN + bidx];
    }

    float m = fmaxf(fmaxf(sc[0], sc[1]), fmaxf(sc[2], sc[3]));
    float e0 = expf(sc[0] - m), e1 = expf(sc[1] - m),
          e2 = expf(sc[2] - m), e3 = expf(sc[3] - m);
    float denom = e0 + e1 + e2 + e3;
    float o = (e0 * vs[0] + e1 * vs[1] + e2 * vs[2] + e3 * vs[3]) / denom;
    outb[((size_t)(b * NHH + h) * HDD + lane) * NN + n] = o;
}

// ---------------- launch ----------------
extern "C" void kernel_launch(void* const* d_in, const int* in_sizes, int n_in,
                              void* d_out, int out_size)
{
    const float* local_feat    = (const float*)d_in[0];
    const float* context_prior = (const float*)d_in[1];
    const float* deformable_x  = (const float*)d_in[2];
    const float* W_q   = (const float*)d_in[3];
    const float* W_k   = (const float*)d_in[4];
    const float* W_v   = (const float*)d_in[5];
    const float* W_pre = (const float*)d_in[6];
    const float* ln1_g = (const float*)d_in[7];
    const float* ln1_b = (const float*)d_in[8];
    const float* W_post= (const float*)d_in[9];
    const float* dw_w  = (const float*)d_in[10];
    const float* dw_b  = (const float*)d_in[11];
    const float* ln2_g = (const float*)d_in[12];
    const float* ln2_b = (const float*)d_in[13];
    const float* W_lo  = (const float*)d_in[14];
    const float* b_lo  = (const float*)d_in[15];
    const float* W_off = (const float*)d_in[16];
    const float* b_off = (const float*)d_in[17];
    const float* abias = (const float*)d_in[18];
    const float* W_p   = (const float*)d_in[19];
    const float* bn_g  = (const float*)d_in[20];
    const float* bn_b  = (const float*)d_in[21];
    const float* bn_m  = (const float*)d_in[22];
    const float* bn_v  = (const float*)d_in[23];
    float* out = (float*)d_out;

    float *q, *cg, *k, *v, *dw, *ao, *pool, *gs, *guide, *off;
    cudaGetSymbolAddress((void**)&q,     g_q);
    cudaGetSymbolAddress((void**)&cg,    g_cg);
    cudaGetSymbolAddress((void**)&k,     g_k);
    cudaGetSymbolAddress((void**)&v,     g_v);
    cudaGetSymbolAddress((void**)&dw,    g_dw);
    cudaGetSymbolAddress((void**)&ao,    g_ao);
    cudaGetSymbolAddress((void**)&pool,  g_pool);
    cudaGetSymbolAddress((void**)&gs,    g_gs);
    cudaGetSymbolAddress((void**)&guide, g_guide);
    cudaGetSymbolAddress((void**)&off,   g_off);

    dim3 gb(NN / 64, CC / 64, BB);   // (36, 6, 8)

    gemm384_kernel<<<gb, 256>>>(W_q,   local_feat,    q,  0, nullptr, nullptr, nullptr, nullptr);
    gemm384_kernel<<<gb, 256>>>(W_pre, context_prior, cg, 1, nullptr, nullptr, nullptr, nullptr);
    gemm384_kernel<<<gb, 256>>>(W_k,   context_prior, k,  0, nullptr, nullptr, nullptr, nullptr);
    gemm384_kernel<<<gb, 256>>>(W_v,   deformable_x,  v,  0, nullptr, nullptr, nullptr, nullptr);

    pool_kernel<<<(BB * CC * 49 + 255) / 256, 256>>>(cg, pool);
    ln1_post_kernel<<<BB * 49, CC>>>(pool, ln1_g, ln1_b, W_post, gs);
    upsample_kernel<<<(BB * 32 * NN + 255) / 256, 256>>>(gs, guide);

    dwconv_kernel<<<(BB * CC * NN + 255) / 256, 256>>>(local_feat, dw_w, dw_b, dw);
    offsets_kernel<<<BB * NN, CC>>>(dw, ln2_g, ln2_b, W_lo, b_lo, guide, W_off, b_off, off);

    attn_kernel<<<(BB * NHH * NN) / 8, 256>>>(q, k, v, off, abias, ao);

    gemm384_kernel<<<gb, 256>>>(W_p, ao, out, 2, bn_g, bn_b, bn_m, bn_v);
}

// round 2
// speedup vs baseline: 5.9600x; 5.9600x over previous
#include <cuda_runtime.h>
#include <math.h>

// ---------------- problem constants ----------------
#define BB   8
#define CC   384
#define HH   48
#define WW   48
#define NN   2304          // HH*WW
#define NHH  12
#define NPP  4
#define HDD  32
#define SCALE_F 0.17677669529663687f   // 1/sqrt(32)

// ---------------- scratch ----------------
__device__ float g_q    [BB*CC*NN];
__device__ float g_cg   [BB*CC*NN];
__device__ float g_k    [BB*CC*NN];
__device__ float g_v    [BB*CC*NN];
__device__ float g_dw   [BB*CC*NN];
__device__ float g_ao   [BB*CC*NN];
__device__ float g_qt   [BB*CC*NN];
__device__ float g_kt   [BB*CC*NN];
__device__ float g_vt   [BB*CC*NN];
__device__ float g_aot  [BB*CC*NN];
__device__ float g_dwt  [BB*CC*NN];
__device__ float g_xgt  [BB*CC*NN];
__device__ float g_off  [BB*96*NN];
__device__ float g_pool [BB*CC*49];
__device__ float g_og   [BB*96*49];
__device__ float g_Wcomb[96*CC];
__device__ float g_cbias[96];

__device__ __forceinline__ float gelu_f(float x) {
    return 0.5f * x * (1.0f + erff(x * 0.7071067811865476f));
}

// ---------------- SGEMM 128x128x8, 8x8 microtile ----------------
// out[b,o,n] = sum_c W[o,c]*in[b,c,n]; mode 0 plain, 1 gelu, 2 batchnorm
__global__ void gemm_kernel(const float* __restrict__ Wm,
                            const float* __restrict__ in,
                            float* __restrict__ out,
                            int mode,
                            const float* __restrict__ bng,
                            const float* __restrict__ bnb,
                            const float* __restrict__ bnm,
                            const float* __restrict__ bnv)
{
    __shared__ float As[8][128];
    __shared__ float Bs[8][128];

    const int tid = threadIdx.x;          // 0..255
    const int tx  = tid & 15;             // n dir
    const int ty  = tid >> 4;             // o dir
    const int n0  = blockIdx.x * 128;
    const int o0  = blockIdx.y * 128;
    const int b   = blockIdx.z;
    const float* inb = in + (size_t)b * CC * NN;

    const int ar = tid >> 1;              // A row (o), 0..127
    const int ah = (tid & 1) * 4;         // A col offset in k
    const int br = tid >> 5;              // B row (k), 0..7
    const int bc = (tid & 31) * 4;        // B col (n)

    float4 aref = *(const float4*)&Wm[(size_t)(o0 + ar) * CC + ah];
    float4 bref = *(const float4*)&inb[(size_t)br * NN + n0 + bc];

    float acc[8][8];
#pragma unroll
    for (int i = 0; i < 8; i++)
#pragma unroll
        for (int j = 0; j < 8; j++) acc[i][j] = 0.f;

    for (int kb = 0; kb < CC; kb += 8) {
        As[ah + 0][ar] = aref.x;
        As[ah + 1][ar] = aref.y;
        As[ah + 2][ar] = aref.z;
        As[ah + 3][ar] = aref.w;
        *(float4*)&Bs[br][bc] = bref;
        __syncthreads();

        if (kb + 8 < CC) {
            aref = *(const float4*)&Wm[(size_t)(o0 + ar) * CC + kb + 8 + ah];
            bref = *(const float4*)&inb[(size_t)(kb + 8 + br) * NN + n0 + bc];
        }

#pragma unroll
        for (int kk = 0; kk < 8; kk++) {
            float a[8], bv[8];
            *(float4*)&a[0]  = *(float4*)&As[kk][ty * 8];
            *(float4*)&a[4]  = *(float4*)&As[kk][ty * 8 + 4];
            *(float4*)&bv[0] = *(float4*)&Bs[kk][tx * 8];
            *(float4*)&bv[4] = *(float4*)&Bs[kk][tx * 8 + 4];
#pragma unroll
            for (int i = 0; i < 8; i++)
#pragma unroll
                for (int j = 0; j < 8; j++) acc[i][j] += a[i] * bv[j];
        }
        __syncthreads();
    }

    float* outb = out + (size_t)b * CC * NN;
#pragma unroll
    for (int i = 0; i < 8; i++) {
        int o = o0 + ty * 8 + i;
        float gg = 1.f, bb2 = 0.f, mm = 0.f, iv = 1.f;
        if (mode == 2) {
            gg = bng[o]; bb2 = bnb[o]; mm = bnm[o];
            iv = rsqrtf(bnv[o] + 1e-5f);
        }
        float r[8];
#pragma unroll
        for (int j = 0; j < 8; j++) {
            float v = acc[i][j];
            if (mode == 1) v = gelu_f(v);
            else if (mode == 2) v = gg * (v - mm) * iv + bb2;
            r[j] = v;
        }
        float* orow = outb + (size_t)o * NN + n0 + tx * 8;
        *(float4*)&orow[0] = *(float4*)&r[0];
        *(float4*)&orow[4] = *(float4*)&r[4];
    }
}

// ---------------- generic tiled transpose: [G,R,C] -> [G,C,R] ----------------
__global__ void transpose_kernel(const float* __restrict__ in,
                                 float* __restrict__ out, int R, int C)
{
    __shared__ float tile[32][33];
    int g  = blockIdx.z;
    int r0 = blockIdx.y * 32;
    int c0 = blockIdx.x * 32;
    const float* ing = in  + (size_t)g * R * C;
    float*       outg = out + (size_t)g * R * C;
    int tx = threadIdx.x & 31;
    int ty = threadIdx.x >> 5;   // 0..7
#pragma unroll
    for (int i = 0; i < 4; i++) {
        int r = ty + i * 8;
        tile[r][tx] = ing[(size_t)(r0 + r) * C + c0 + tx];
    }
    __syncthreads();
#pragma unroll
    for (int i = 0; i < 4; i++) {
        int r = ty + i * 8;
        outg[(size_t)(c0 + r) * R + r0 + tx] = tile[tx][r];
    }
}

// ---------------- adaptive avg pool 48x48 -> 7x7 ----------------
__global__ void pool_kernel(const float* __restrict__ in, float* __restrict__ out)
{
    int idx = blockIdx.x * blockDim.x + threadIdx.x;
    if (idx >= BB * CC * 49) return;
    int p = idx % 7;
    int o = (idx / 7) % 7;
    int c = (idx / 49) % CC;
    int b = idx / (49 * CC);
    int sy = o * HH / 7, ey = ((o + 1) * HH + 6) / 7;
    int sx = p * WW / 7, ex = ((p + 1) * WW + 6) / 7;
    const float* f = in + ((size_t)b * CC + c) * NN;
    float s = 0.f;
    for (int y = sy; y < ey; y++)
        for (int x = sx; x < ex; x++)
            s += f[y * WW + x];
    out[idx] = s / (float)((ey - sy) * (ex - sx));
}

// ---------------- LN1 + W_post + W_off_guide fused -> og[b,96,49] ----------------
__global__ void ln1_post_og_kernel(const float* __restrict__ pool,
                                   const float* __restrict__ g1,
                                   const float* __restrict__ b1,
                                   const float* __restrict__ Wpost,
                                   const float* __restrict__ Woff,
                                   float* __restrict__ og)
{
    __shared__ float rs[CC], rq[CC], xn[CC];
    __shared__ float gsv[32];
    __shared__ float s_mu, s_rstd;
    int t = threadIdx.x;                   // 0..383
    int b = blockIdx.x / 49;
    int s = blockIdx.x % 49;

    float x = pool[((size_t)b * CC + t) * 49 + s];
    rs[t] = x; rq[t] = x * x;
    __syncthreads();
    for (int st = 192; st >= 6; st >>= 1) {
        if (t < st) { rs[t] += rs[t + st]; rq[t] += rq[t + st]; }
        __syncthreads();
    }
    if (t == 0) {
        float a = 0.f, q = 0.f;
        for (int i = 0; i < 6; i++) { a += rs[i]; q += rq[i]; }
        float mu = a / CC;
        float var = q / CC - mu * mu;
        s_mu = mu; s_rstd = rsqrtf(var + 1e-6f);
    }
    __syncthreads();
    xn[t] = (x - s_mu) * s_rstd * g1[t] + b1[t];
    __syncthreads();
    if (t < 32) {
        float acc = 0.f;
        const float* wr = Wpost + (size_t)t * CC;
        for (int c = 0; c < CC; c++) acc += wr[c] * xn[c];
        gsv[t] = acc;
    }
    __syncthreads();
    if (t < 96) {
        float a = 0.f;
        const float* wr = Woff + (size_t)t * 64;   // guide cols 0..31
#pragma unroll
        for (int i = 0; i < 32; i++) a += wr[i] * gsv[i];
        og[((size_t)b * 96 + t) * 49 + s] = a;
    }
}

// ---------------- 3x3 depthwise conv + bias ----------------
__global__ void dwconv_kernel(const float* __restrict__ in,
                              const float* __restrict__ w,
                              const float* __restrict__ bias,
                              float* __restrict__ out)
{
    int idx = blockIdx.x * blockDim.x + threadIdx.x;
    if (idx >= BB * CC * NN) return;
    int x = idx % WW;
    int y = (idx / WW) % HH;
    int c = (idx / NN) % CC;
    int b = idx / (NN * CC);
    const float* f  = in + ((size_t)b * CC + c) * NN;
    const float* wc = w + (size_t)c * 9;
    float s = 0.f;
#pragma unroll
    for (int dy = 0; dy < 3; dy++) {
        int yy = y + dy - 1;
        if (yy < 0 || yy >= HH) continue;
#pragma unroll
        for (int dx = 0; dx < 3; dx++) {
            int xx = x + dx - 1;
            if (xx < 0 || xx >= WW) continue;
            s += f[yy * WW + xx] * wc[dy * 3 + dx];
        }
    }
    out[idx] = s + bias[c];
}

// ---------------- LN2 + gelu, on [b,n,c] layout (warp per pixel) ----------------
__global__ void ln2gelu_kernel(const float* __restrict__ dwt,
                               const float* __restrict__ g2,
                               const float* __restrict__ b2,
                               float* __restrict__ xgt)
{
    int gw = (blockIdx.x * blockDim.x + threadIdx.x) >> 5;
    int lane = threadIdx.x & 31;
    if (gw >= BB * NN) return;
    const float* row = dwt + (size_t)gw * CC;
    float v[12];
    float s = 0.f, q = 0.f;
#pragma unroll
    for (int j = 0; j < 12; j++) {
        v[j] = row[lane + 32 * j];
        s += v[j]; q += v[j] * v[j];
    }
#pragma unroll
    for (int st = 16; st > 0; st >>= 1) {
        s += __shfl_xor_sync(0xffffffffu, s, st);
        q += __shfl_xor_sync(0xffffffffu, q, st);
    }
    float mu = s / CC;
    float var = q / CC - mu * mu;
    float rstd = rsqrtf(var + 1e-6f);
    float* orow = xgt + (size_t)gw * CC;
#pragma unroll
    for (int j = 0; j < 12; j++) {
        int c = lane + 32 * j;
        orow[c] = gelu_f((v[j] - mu) * rstd * g2[c] + b2[c]);
    }
}

// ---------------- precompute Wcomb = Woff[:,32:64]@Wlo, cbias ----------------
__global__ void combinew_kernel(const float* __restrict__ Woff,
                                const float* __restrict__ Wlo,
                                const float* __restrict__ blo,
                                const float* __restrict__ boff,
                                float* __restrict__ Wcomb,
                                float* __restrict__ cbias)
{
    int o = blockIdx.x;          // 0..95
    int c = threadIdx.x;         // 0..383
    float acc = 0.f;
#pragma unroll
    for (int i = 0; i < 32; i++)
        acc += Woff[o * 64 + 32 + i] * Wlo[(size_t)i * CC + c];
    Wcomb[(size_t)o * CC + c] = acc;
    if (c == 0) {
        float s2 = boff[o];
        for (int i = 0; i < 32; i++) s2 += Woff[o * 64 + 32 + i] * blo[i];
        cbias[o] = s2;
    }
}

// ---------------- offsets GEMM: off[b,96,n] = Wcomb@xgt^T + bilerp(og) + cbias ----------------
__global__ void gemmoff_kernel(const float* __restrict__ Wcomb,
                               const float* __restrict__ xgt,
                               const float* __restrict__ og,
                               const float* __restrict__ cbias,
                               float* __restrict__ off)
{
    __shared__ float As[16][96];
    __shared__ float Bs[16][64];
    int tid = threadIdx.x;                 // 0..255
    int tx = tid & 15, ty = tid >> 4;      // tx: n (4 each), ty: o (6 each)
    int n0 = blockIdx.x * 64;
    int b  = blockIdx.y;
    const float* xb = xgt + (size_t)b * NN * CC;

    float acc[6][4];
#pragma unroll
    for (int i = 0; i < 6; i++)
#pragma unroll
        for (int j = 0; j < 4; j++) acc[i][j] = 0.f;

    for (int kb = 0; kb < CC; kb += 16) {
#pragma unroll
        for (int s = 0; s < 6; s++) {
            int idx = tid + s * 256;       // < 1536
            As[idx & 15][idx >> 4] = Wcomb[(size_t)(idx >> 4) * CC + kb + (idx & 15)];
        }
#pragma unroll
        for (int s = 0; s < 4; s++) {
            int idx = tid + s * 256;       // < 1024
            Bs[idx & 15][idx >> 4] = xb[(size_t)(n0 + (idx >> 4)) * CC + kb + (idx & 15)];
        }
        __syncthreads();
#pragma unroll
        for (int kk = 0; kk < 16; kk++) {
            float a[6], bv[4];
#pragma unroll
            for (int i = 0; i < 6; i++) a[i] = As[kk][ty * 6 + i];
#pragma unroll
            for (int j = 0; j < 4; j++) bv[j] = Bs[kk][tx * 4 + j];
#pragma unroll
            for (int i = 0; i < 6; i++)
#pragma unroll
                for (int j = 0; j < 4; j++) acc[i][j] += a[i] * bv[j];
        }
        __syncthreads();
    }

#pragma unroll
    for (int j = 0; j < 4; j++) {
        int n = n0 + tx * 4 + j;
        int y = n / WW, x = n % WW;
        float sy = fminf(fmaxf((y + 0.5f) * (7.0f / 48.0f) - 0.5f, 0.f), 6.f);
        float sx = fminf(fmaxf((x + 0.5f) * (7.0f / 48.0f) - 0.5f, 0.f), 6.f);
        int i0y = (int)floorf(sy); int i1y = min(i0y + 1, 6); float fy = sy - i0y;
        int i0x = (int)floorf(sx); int i1x = min(i0x + 1, 6); float fx = sx - i0x;
        float w00 = (1.f - fy) * (1.f - fx), w01 = (1.f - fy) * fx;
        float w10 = fy * (1.f - fx), w11 = fy * fx;
#pragma unroll
        for (int i = 0; i < 6; i++) {
            int o = ty * 6 + i;
            const float* ogp = og + ((size_t)b * 96 + o) * 49;
            float gv = w00 * ogp[i0y * 7 + i0x] + w01 * ogp[i0y * 7 + i1x]
                     + w10 * ogp[i1y * 7 + i0x] + w11 * ogp[i1y * 7 + i1x];
            off[((size_t)b * 96 + o) * NN + n] = acc[i][j] + gv + cbias[o];
        }
    }
}

// ---------------- fused deformable attention (coalesced [b,h,n,d]) ----------------
__global__ void attn_kernel(const float* __restrict__ qt,
                            const float* __restrict__ kt,
                            const float* __restrict__ vt,
                            const float* __restrict__ offb,
                            const float* __restrict__ abias,
                            float* __restrict__ aot)
{
    int gw   = (blockIdx.x * blockDim.x + threadIdx.x) >> 5;
    int lane = threadIdx.x & 31;
    if (gw >= BB * NHH * NN) return;
    int n = gw % NN;
    int h = (gw / NN) % NHH;
    int b = gw / (NN * NHH);
    int qx = n % WW;
    int qy = n / WW;

    size_t head = (size_t)(b * NHH + h) * NN;
    const float* kf = kt + head * HDD;
    const float* vf = vt + head * HDD;
    float qv = qt[(head + n) * HDD + lane];

    float ov = 0.f;
    if (lane < 8) ov = offb[((size_t)(b * 96 + h * 8 + lane)) * NN + n];

    float sc[NPP], vs[NPP];
#pragma unroll
    for (int p = 0; p < NPP; p++) {
        float ox = __shfl_sync(0xffffffffu, ov, 2 * p);
        float oy = __shfl_sync(0xffffffffu, ov, 2 * p + 1);
        float gx = (((float)qx + 0.5f) / (float)WW + ox / (float)WW) * 2.0f - 1.0f;
        float gy = (((float)qy + 0.5f) / (float)HH + oy / (float)HH) * 2.0f - 1.0f;
        float x = (gx + 1.0f) * 0.5f * (float)WW - 0.5f;
        float y = (gy + 1.0f) * 0.5f * (float)HH - 0.5f;
        float x0f = floorf(x), y0f = floorf(y);
        float fx = x - x0f, fy = y - y0f;
        int x0 = (int)x0f, y0 = (int)y0f;
        int x1 = x0 + 1,  y1 = y0 + 1;
        bool vx0 = (x0 >= 0 && x0 < WW), vx1 = (x1 >= 0 && x1 < WW);
        bool vy0 = (y0 >= 0 && y0 < HH), vy1 = (y1 >= 0 && y1 < HH);
        float w00 = (1.f - fx) * (1.f - fy);
        float w01 = fx * (1.f - fy);
        float w10 = (1.f - fx) * fy;
        float w11 = fx * fy;

        float ks = 0.f, vsmp = 0.f;
        if (vx0 && vy0) { size_t i = (size_t)(y0 * WW + x0) * HDD + lane; ks += w00 * kf[i]; vsmp += w00 * vf[i]; }
        if (vx1 && vy0) { size_t i = (size_t)(y0 * WW + x1) * HDD + lane; ks += w01 * kf[i]; vsmp += w01 * vf[i]; }
        if (vx0 && vy1) { size_t i = (size_t)(y1 * WW + x0) * HDD + lane; ks += w10 * kf[i]; vsmp += w10 * vf[i]; }
        if (vx1 && vy1) { size_t i = (size_t)(y1 * WW + x1) * HDD + lane; ks += w11 * kf[i]; vsmp += w11 * vf[i]; }
        vs[p] = vsmp;

        float part = qv * ks;
#pragma unroll
        for (int s = 16; s > 0; s >>= 1)
            part += __shfl_xor_sync(0xffffffffu, part, s);

        int px = (int)rintf(x); px = min(max(px, 0), WW - 1);
        int py = (int)rintf(y); py = min(max(py, 0), HH - 1);
        int bidx = abs(qy - py) * WW + abs(qx - px);
        sc[p] = part * SCALE_F + abias[h * NN + bidx];
    }

    float m = fmaxf(fmaxf(sc[0], sc[1]), fmaxf(sc[2], sc[3]));
    float e0 = expf(sc[0] - m), e1 = expf(sc[1] - m),
          e2 = expf(sc[2] - m), e3 = expf(sc[3] - m);
    float denom = e0 + e1 + e2 + e3;
    float o = (e0 * vs[0] + e1 * vs[1] + e2 * vs[2] + e3 * vs[3]) / denom;
    aot[(head + n) * HDD + lane] = o;
}

// ---------------- launch ----------------
extern "C" void kernel_launch(void* const* d_in, const int* in_sizes, int n_in,
                              void* d_out, int out_size)
{
    const float* local_feat    = (const float*)d_in[0];
    const float* context_prior = (const float*)d_in[1];
    const float* deformable_x  = (const float*)d_in[2];
    const float* W_q   = (const float*)d_in[3];
    const float* W_k   = (const float*)d_in[4];
    const float* W_v   = (const float*)d_in[5];
    const float* W_pre = (const float*)d_in[6];
    const float* ln1_g = (const float*)d_in[7];
    const float* ln1_b = (const float*)d_in[8];
    const float* W_post= (const float*)d_in[9];
    const float* dw_w  = (const float*)d_in[10];
    const float* dw_b  = (const float*)d_in[11];
    const float* ln2_g = (const float*)d_in[12];
    const float* ln2_b = (const float*)d_in[13];
    const float* W_lo  = (const float*)d_in[14];
    const float* b_lo  = (const float*)d_in[15];
    const float* W_off = (const float*)d_in[16];
    const float* b_off = (const float*)d_in[17];
    const float* abias = (const float*)d_in[18];
    const float* W_p   = (const float*)d_in[19];
    const float* bn_g  = (const float*)d_in[20];
    const float* bn_b  = (const float*)d_in[21];
    const float* bn_m  = (const float*)d_in[22];
    const float* bn_v  = (const float*)d_in[23];
    float* out = (float*)d_out;

    float *q, *cg, *k, *v, *dw, *ao, *qt, *kt, *vt, *aot, *dwt, *xgt;
    float *off, *pool, *og, *Wcomb, *cbias;
    cudaGetSymbolAddress((void**)&q,     g_q);
    cudaGetSymbolAddress((void**)&cg,    g_cg);
    cudaGetSymbolAddress((void**)&k,     g_k);
    cudaGetSymbolAddress((void**)&v,     g_v);
    cudaGetSymbolAddress((void**)&dw,    g_dw);
    cudaGetSymbolAddress((void**)&ao,    g_ao);
    cudaGetSymbolAddress((void**)&qt,    g_qt);
    cudaGetSymbolAddress((void**)&kt,    g_kt);
    cudaGetSymbolAddress((void**)&vt,    g_vt);
    cudaGetSymbolAddress((void**)&aot,   g_aot);
    cudaGetSymbolAddress((void**)&dwt,   g_dwt);
    cudaGetSymbolAddress((void**)&xgt,   g_xgt);
    cudaGetSymbolAddress((void**)&off,   g_off);
    cudaGetSymbolAddress((void**)&pool,  g_pool);
    cudaGetSymbolAddress((void**)&og,    g_og);
    cudaGetSymbolAddress((void**)&Wcomb, g_Wcomb);
    cudaGetSymbolAddress((void**)&cbias, g_cbias);

    dim3 gb(NN / 128, CC / 128, BB);       // (18, 3, 8)

    gemm_kernel<<<gb, 256>>>(W_q,   local_feat,    q,  0, nullptr, nullptr, nullptr, nullptr);
    gemm_kernel<<<gb, 256>>>(W_pre, context_prior, cg, 1, nullptr, nullptr, nullptr, nullptr);
    gemm_kernel<<<gb, 256>>>(W_k,   context_prior, k,  0, nullptr, nullptr, nullptr, nullptr);
    gemm_kernel<<<gb, 256>>>(W_v,   deformable_x,  v,  0, nullptr, nullptr, nullptr, nullptr);

    // q/k/v [b,c,n] -> [b,h,n,d]  (per (b,h): transpose 32 x 2304)
    dim3 tq(NN / 32, 1, BB * NHH);
    transpose_kernel<<<tq, 256>>>(q, qt, 32, NN);
    transpose_kernel<<<tq, 256>>>(k, kt, 32, NN);
    transpose_kernel<<<tq, 256>>>(v, vt, 32, NN);

    pool_kernel<<<(BB * CC * 49 + 255) / 256, 256>>>(cg, pool);
    ln1_post_og_kernel<<<BB * 49, CC>>>(pool, ln1_g, ln1_b, W_post, W_off, og);

    dwconv_kernel<<<(BB * CC * NN + 255) / 256, 256>>>(local_feat, dw_w, dw_b, dw);
    // dw [b,c,n] -> [b,n,c]  (per b: transpose 384 x 2304)
    dim3 td(NN / 32, CC / 32, BB);
    transpose_kernel<<<td, 256>>>(dw, dwt, CC, NN);
    ln2gelu_kernel<<<(BB * NN) / 8, 256>>>(dwt, ln2_g, ln2_b, xgt);

    combinew_kernel<<<96, CC>>>(W_off, W_lo, b_lo, b_off, Wcomb, cbias);
    dim3 go(NN / 64, BB);
    gemmoff_kernel<<<go, 256>>>(Wcomb, xgt, og, cbias, off);

    attn_kernel<<<(BB * NHH * NN) / 8, 256>>>(qt, kt, vt, off, abias, aot);

    // aot [b,h,n,d] -> ao [b,c,n]  (per (b,h): transpose 2304 x 32)
    dim3 tb(1, NN / 32, BB * NHH);
    transpose_kernel<<<tb, 256>>>(aot, ao, NN, 32);

    gemm_kernel<<<gb, 256>>>(W_p, ao, out, 2, bn_g, bn_b, bn_m, bn_v);
}

// round 5
// speedup vs baseline: 9.4558x; 1.5865x over previous
#include <cuda_runtime.h>
#include <cuda_bf16.h>
#include <math.h>
#include <stdint.h>

// ---------------- problem constants ----------------
#define BB   8
#define CC   384
#define HH   48
#define WW   48
#define NN   2304
#define NHH  12
#define NPP  4
#define HDD  32
#define SCALE_F 0.17677669529663687f

// ---------------- scratch ----------------
__device__ float g_cg   [BB*CC*NN];
__device__ float g_qt   [BB*CC*NN];
__device__ float g_kt   [BB*CC*NN];
__device__ float g_vt   [BB*CC*NN];
__device__ float g_aot  [BB*CC*NN];   // attn out, [b][n][c]
__device__ float g_dw   [BB*CC*NN];
__device__ float g_dwt  [BB*CC*NN];
__device__ float g_xgt  [BB*CC*NN];
__device__ float g_off  [BB*96*NN];
__device__ float g_pool [BB*CC*49];
__device__ float g_og   [BB*96*49];
__device__ float g_Wcomb[96*CC];
__device__ float g_cbias[96];
__device__ __nv_bfloat16 g_wh[5*CC*CC];
__device__ __nv_bfloat16 g_wl[5*CC*CC];
__device__ __nv_bfloat16 g_bh[BB*NN*CC];   // activations [b][n][c] hi
__device__ __nv_bfloat16 g_bl[BB*NN*CC];   // lo

__device__ __forceinline__ float gelu_f(float x) {
    return 0.5f * x * (1.0f + erff(x * 0.7071067811865476f));
}

__device__ __forceinline__ uint32_t smem_u32(const void* p) {
    uint32_t a;
    asm("{ .reg .u64 t; cvta.to.shared.u64 t, %1; cvt.u32.u64 %0, t; }" : "=r"(a) : "l"(p));
    return a;
}
__device__ __forceinline__ void ldmx4(uint32_t* r, uint32_t addr) {
    asm volatile("ldmatrix.sync.aligned.m8n8.x4.shared.b16 {%0,%1,%2,%3}, [%4];"
        : "=r"(r[0]), "=r"(r[1]), "=r"(r[2]), "=r"(r[3]) : "r"(addr));
}
__device__ __forceinline__ void mma_bf16(float* d, const uint32_t* a, const uint32_t* b) {
    asm volatile("mma.sync.aligned.m16n8k16.row.col.f32.bf16.bf16.f32 "
        "{%0,%1,%2,%3}, {%4,%5,%6,%7}, {%8,%9}, {%0,%1,%2,%3};"
        : "+f"(d[0]), "+f"(d[1]), "+f"(d[2]), "+f"(d[3])
        : "r"(a[0]), "r"(a[1]), "r"(a[2]), "r"(a[3]), "r"(b[0]), "r"(b[1]));
}

// ---------------- bf16x3 tensor-core GEMM ----------------
// out[o][n] = sum_c W[o][c] * Bt[n][c]   (Bt = activations in [b][n][c])
// omode 0: out [b,o,n]   omode 1: out [b,h,n,d] (h=o>>5, d=o&31)
// emode 0: none  1: gelu  2: batchnorm
#define SMEM_DYN 49152

__global__ __launch_bounds__(256) void gemm_mma(
    const __nv_bfloat16* __restrict__ Wh, const __nv_bfloat16* __restrict__ Wl,
    const __nv_bfloat16* __restrict__ Bth, const __nv_bfloat16* __restrict__ Btl,
    float* __restrict__ out, int omode, int emode,
    const float* __restrict__ bng, const float* __restrict__ bnb,
    const float* __restrict__ bnm, const float* __restrict__ bnv)
{
    extern __shared__ char smem[];
    const uint32_t sb = smem_u32(smem);
    const int tid = threadIdx.x, wid = tid >> 5, lane = tid & 31;
    const int n0 = blockIdx.x * 128, o0 = blockIdx.y * 128, b = blockIdx.z;
    const int m0w = (wid >> 2) * 64, n0w = (wid & 3) * 32;

    // staging: each thread owns one uint4 (8 bf16) per tile-part per chunk
    const int ldrow = tid >> 1, ldhalf = tid & 1;
    const __nv_bfloat16* gAh = Wh + (size_t)(o0 + ldrow) * CC + ldhalf * 8;
    const __nv_bfloat16* gAl = Wl + (size_t)(o0 + ldrow) * CC + ldhalf * 8;
    const __nv_bfloat16* gBh = Bth + ((size_t)b * NN + n0 + ldrow) * CC + ldhalf * 8;
    const __nv_bfloat16* gBl = Btl + ((size_t)b * NN + n0 + ldrow) * CC + ldhalf * 8;
    const uint32_t stoff = (uint32_t)(ldrow * 48 + ldhalf * 16);

    // ldmatrix lane addresses (48B row stride => conflict-free)
    const uint32_t aoff = (uint32_t)((m0w + (lane & 7) + ((lane >> 3) & 1) * 8) * 48
                                     + (lane >> 4) * 16);
    const uint32_t boff = (uint32_t)((n0w + (lane >> 4) * 8 + (lane & 7)) * 48
                                     + ((lane >> 3) & 1) * 16);

    float acc[4][4][4];
#pragma unroll
    for (int i = 0; i < 4; i++)
#pragma unroll
        for (int j = 0; j < 4; j++)
#pragma unroll
            for (int e = 0; e < 4; e++) acc[i][j][e] = 0.f;

    uint4 pAh = *(const uint4*)gAh;
    uint4 pAl = *(const uint4*)gAl;
    uint4 pBh = *(const uint4*)gBh;
    uint4 pBl = *(const uint4*)gBl;
    *(uint4*)(smem + stoff)         = pAh;
    *(uint4*)(smem + 6144  + stoff) = pAl;
    *(uint4*)(smem + 12288 + stoff) = pBh;
    *(uint4*)(smem + 18432 + stoff) = pBl;
    __syncthreads();

    for (int kc = 0; kc < 24; kc++) {
        const uint32_t cur = (uint32_t)(kc & 1) * 24576u;
        if (kc < 23) {
            int ko = (kc + 1) * 16;
            pAh = *(const uint4*)(gAh + ko);
            pAl = *(const uint4*)(gAl + ko);
            pBh = *(const uint4*)(gBh + ko);
            pBl = *(const uint4*)(gBl + ko);
        }
        uint32_t ah[4][4], al[4][4], bfh[4][2], bfl[4][2];
#pragma unroll
        for (int mt = 0; mt < 4; mt++) {
            ldmx4(ah[mt], sb + cur + aoff + mt * 768);
            ldmx4(al[mt], sb + cur + 6144 + aoff + mt * 768);
        }
#pragma unroll
        for (int pr = 0; pr < 2; pr++) {
            uint32_t t[4];
            ldmx4(t, sb + cur + 12288 + boff + pr * 768);
            bfh[pr*2][0] = t[0]; bfh[pr*2][1] = t[1];
            bfh[pr*2+1][0] = t[2]; bfh[pr*2+1][1] = t[3];
            ldmx4(t, sb + cur + 18432 + boff + pr * 768);
            bfl[pr*2][0] = t[0]; bfl[pr*2][1] = t[1];
            bfl[pr*2+1][0] = t[2]; bfl[pr*2+1][1] = t[3];
        }
#pragma unroll
        for (int mt = 0; mt < 4; mt++)
#pragma unroll
            for (int nt = 0; nt < 4; nt++) {
                mma_bf16(acc[mt][nt], ah[mt], bfh[nt]);
                mma_bf16(acc[mt][nt], ah[mt], bfl[nt]);
                mma_bf16(acc[mt][nt], al[mt], bfh[nt]);
            }
        if (kc < 23) {
            const uint32_t nxt = (uint32_t)((kc + 1) & 1) * 24576u;
            *(uint4*)(smem + nxt + stoff)         = pAh;
            *(uint4*)(smem + nxt + 6144  + stoff) = pAl;
            *(uint4*)(smem + nxt + 12288 + stoff) = pBh;
            *(uint4*)(smem + nxt + 18432 + stoff) = pBl;
        }
        __syncthreads();
    }

    // epilogue: direct stores from accumulators
    if (omode == 0) {
        float* outb = out + (size_t)b * CC * NN;
#pragma unroll
        for (int mt = 0; mt < 4; mt++)
#pragma unroll
            for (int half = 0; half < 2; half++) {
                int o = o0 + m0w + mt * 16 + (lane >> 2) + half * 8;
                float s1 = 1.f, s0 = 0.f;
                if (emode == 2) {
                    float iv = rsqrtf(bnv[o] + 1e-5f);
                    s1 = bng[o] * iv;
                    s0 = bnb[o] - bnm[o] * s1;
                }
#pragma unroll
                for (int nt = 0; nt < 4; nt++) {
                    float v0 = acc[mt][nt][half * 2 + 0];
                    float v1 = acc[mt][nt][half * 2 + 1];
                    if (emode == 1) { v0 = gelu_f(v0); v1 = gelu_f(v1); }
                    else if (emode == 2) { v0 = v0 * s1 + s0; v1 = v1 * s1 + s0; }
                    int n = n0 + n0w + nt * 8 + (lane & 3) * 2;
                    *(float2*)&outb[(size_t)o * NN + n] = make_float2(v0, v1);
                }
            }
    } else {
#pragma unroll
        for (int mt = 0; mt < 4; mt++)
#pragma unroll
            for (int half = 0; half < 2; half++) {
                int og = o0 + m0w + mt * 16 + (lane >> 2) + half * 8;
                int h = og >> 5, d = og & 31;
#pragma unroll
                for (int nt = 0; nt < 4; nt++) {
                    int n = n0 + n0w + nt * 8 + (lane & 3) * 2;
                    size_t bi = ((size_t)(b * NHH + h) * NN + n) * 32 + d;
                    out[bi]      = acc[mt][nt][half * 2 + 0];
                    out[bi + 32] = acc[mt][nt][half * 2 + 1];
                }
            }
    }
}

// ---------------- elementwise f32 -> bf16 hi/lo ----------------
__global__ void conv_hilo(const float* __restrict__ in,
                          __nv_bfloat16* __restrict__ oh,
                          __nv_bfloat16* __restrict__ ol)
{
    int i = (blockIdx.x * 256 + threadIdx.x) * 4;
    float4 v = *(const float4*)&in[i];
    __nv_bfloat16 h0 = __float2bfloat16(v.x), h1 = __float2bfloat16(v.y);
    __nv_bfloat16 h2 = __float2bfloat16(v.z), h3 = __float2bfloat16(v.w);
    __nv_bfloat16 l0 = __float2bfloat16(v.x - __bfloat162float(h0));
    __nv_bfloat16 l1 = __float2bfloat16(v.y - __bfloat162float(h1));
    __nv_bfloat16 l2 = __float2bfloat16(v.z - __bfloat162float(h2));
    __nv_bfloat16 l3 = __float2bfloat16(v.w - __bfloat162float(h3));
    __nv_bfloat16 hb[4] = {h0, h1, h2, h3};
    __nv_bfloat16 lb[4] = {l0, l1, l2, l3};
    *(uint2*)&oh[i] = *(uint2*)hb;
    *(uint2*)&ol[i] = *(uint2*)lb;
}

// ---------------- [b][c][n] f32 -> [b][n][c] bf16 hi/lo (transposing) ----------------
__global__ void convbt_kernel(const float* __restrict__ in,
                              __nv_bfloat16* __restrict__ oh,
                              __nv_bfloat16* __restrict__ ol)
{
    __shared__ float sm[64][33];
    int b = blockIdx.z;
    int c0 = blockIdx.y * 64;
    int n0 = blockIdx.x * 32;
    int tid = threadIdx.x;
#pragma unroll
    for (int i = 0; i < 2; i++) {
        int id = tid + 256 * i;           // 0..511
        int c = id >> 3, nch = id & 7;
        float4 v = *(const float4*)&in[((size_t)b * CC + c0 + c) * NN + n0 + nch * 4];
        sm[c][nch * 4 + 0] = v.x;
        sm[c][nch * 4 + 1] = v.y;
        sm[c][nch * 4 + 2] = v.z;
        sm[c][nch * 4 + 3] = v.w;
    }
    __syncthreads();
#pragma unroll
    for (int i = 0; i < 4; i++) {
        int id = tid + 256 * i;           // 0..1023
        int n = id >> 5, cp = id & 31;
        int c = cp * 2;
        float x0 = sm[c][n], x1 = sm[c + 1][n];
        __nv_bfloat16 h0 = __float2bfloat16(x0), h1 = __float2bfloat16(x1);
        __nv_bfloat16 l0 = __float2bfloat16(x0 - __bfloat162float(h0));
        __nv_bfloat16 l1 = __float2bfloat16(x1 - __bfloat162float(h1));
        __nv_bfloat16 hb[2] = {h0, h1};
        __nv_bfloat16 lb[2] = {l0, l1};
        size_t o = ((size_t)b * NN + n0 + n) * CC + c0 + c;
        *(uint32_t*)&oh[o] = *(uint32_t*)hb;
        *(uint32_t*)&ol[o] = *(uint32_t*)lb;
    }
}

// ---------------- adaptive avg pool 48x48 -> 7x7 ----------------
__global__ void pool_kernel(const float* __restrict__ in, float* __restrict__ out)
{
    int idx = blockIdx.x * blockDim.x + threadIdx.x;
    if (idx >= BB * CC * 49) return;
    int p = idx % 7;
    int o = (idx / 7) % 7;
    int c = (idx / 49) % CC;
    int b = idx / (49 * CC);
    int sy = o * HH / 7, ey = ((o + 1) * HH + 6) / 7;
    int sx = p * WW / 7, ex = ((p + 1) * WW + 6) / 7;
    const float* f = in + ((size_t)b * CC + c) * NN;
    float s = 0.f;
    for (int y = sy; y < ey; y++)
        for (int x = sx; x < ex; x++)
            s += f[y * WW + x];
    out[idx] = s / (float)((ey - sy) * (ex - sx));
}

// ---------------- LN1 + W_post + W_off_guide fused -> og[b,96,49] ----------------
__global__ void ln1_post_og_kernel(const float* __restrict__ pool,
                                   const float* __restrict__ g1,
                                   const float* __restrict__ b1,
                                   const float* __restrict__ Wpost,
                                   const float* __restrict__ Woff,
                                   float* __restrict__ og)
{
    __shared__ float rs[CC], rq[CC], xn[CC];
    __shared__ float gsv[32];
    __shared__ float s_mu, s_rstd;
    int t = threadIdx.x;
    int b = blockIdx.x / 49;
    int s = blockIdx.x % 49;

    float x = pool[((size_t)b * CC + t) * 49 + s];
    rs[t] = x; rq[t] = x * x;
    __syncthreads();
    for (int st = 192; st >= 6; st >>= 1) {
        if (t < st) { rs[t] += rs[t + st]; rq[t] += rq[t + st]; }
        __syncthreads();
    }
    if (t == 0) {
        float a = 0.f, q = 0.f;
        for (int i = 0; i < 6; i++) { a += rs[i]; q += rq[i]; }
        float mu = a / CC;
        float var = q / CC - mu * mu;
        s_mu = mu; s_rstd = rsqrtf(var + 1e-6f);
    }
    __syncthreads();
    xn[t] = (x - s_mu) * s_rstd * g1[t] + b1[t];
    __syncthreads();
    if (t < 32) {
        float acc = 0.f;
        const float* wr = Wpost + (size_t)t * CC;
        for (int c = 0; c < CC; c++) acc += wr[c] * xn[c];
        gsv[t] = acc;
    }
    __syncthreads();
    if (t < 96) {
        float a = 0.f;
        const float* wr = Woff + (size_t)t * 64;
#pragma unroll
        for (int i = 0; i < 32; i++) a += wr[i] * gsv[i];
        og[((size_t)b * 96 + t) * 49 + s] = a;
    }
}

// ---------------- 3x3 depthwise conv + bias ----------------
__global__ void dwconv_kernel(const float* __restrict__ in,
                              const float* __restrict__ w,
                              const float* __restrict__ bias,
                              float* __restrict__ out)
{
    int idx = blockIdx.x * blockDim.x + threadIdx.x;
    if (idx >= BB * CC * NN) return;
    int x = idx % WW;
    int y = (idx / WW) % HH;
    int c = (idx / NN) % CC;
    int b = idx / (NN * CC);
    const float* f  = in + ((size_t)b * CC + c) * NN;
    const float* wc = w + (size_t)c * 9;
    float s = 0.f;
#pragma unroll
    for (int dy = 0; dy < 3; dy++) {
        int yy = y + dy - 1;
        if (yy < 0 || yy >= HH) continue;
#pragma unroll
        for (int dx = 0; dx < 3; dx++) {
            int xx = x + dx - 1;
            if (xx < 0 || xx >= WW) continue;
            s += f[yy * WW + xx] * wc[dy * 3 + dx];
        }
    }
    out[idx] = s + bias[c];
}

// ---------------- generic tiled transpose: [G,R,C] -> [G,C,R] ----------------
__global__ void transpose_kernel(const float* __restrict__ in,
                                 float* __restrict__ out, int R, int C)
{
    __shared__ float tile[32][33];
    int g  = blockIdx.z;
    int r0 = blockIdx.y * 32;
    int c0 = blockIdx.x * 32;
    const float* ing = in  + (size_t)g * R * C;
    float*       outg = out + (size_t)g * R * C;
    int tx = threadIdx.x & 31;
    int ty = threadIdx.x >> 5;
#pragma unroll
    for (int i = 0; i < 4; i++) {
        int r = ty + i * 8;
        tile[r][tx] = ing[(size_t)(r0 + r) * C + c0 + tx];
    }
    __syncthreads();
#pragma unroll
    for (int i = 0; i < 4; i++) {
        int r = ty + i * 8;
        outg[(size_t)(c0 + r) * R + r0 + tx] = tile[tx][r];
    }
}

// ---------------- LN2 + gelu on [b,n,c] (warp per pixel) ----------------
__global__ void ln2gelu_kernel(const float* __restrict__ dwt,
                               const float* __restrict__ g2,
                               const float* __restrict__ b2,
                               float* __restrict__ xgt)
{
    int gw = (blockIdx.x * blockDim.x + threadIdx.x) >> 5;
    int lane = threadIdx.x & 31;
    if (gw >= BB * NN) return;
    const float* row = dwt + (size_t)gw * CC;
    float v[12];
    float s = 0.f, q = 0.f;
#pragma unroll
    for (int j = 0; j < 12; j++) {
        v[j] = row[lane + 32 * j];
        s += v[j]; q += v[j] * v[j];
    }
#pragma unroll
    for (int st = 16; st > 0; st >>= 1) {
        s += __shfl_xor_sync(0xffffffffu, s, st);
        q += __shfl_xor_sync(0xffffffffu, q, st);
    }
    float mu = s / CC;
    float var = q / CC - mu * mu;
    float rstd = rsqrtf(var + 1e-6f);
    float* orow = xgt + (size_t)gw * CC;
#pragma unroll
    for (int j = 0; j < 12; j++) {
        int c = lane + 32 * j;
        orow[c] = gelu_f((v[j] - mu) * rstd * g2[c] + b2[c]);
    }
}

// ---------------- Wcomb = Woff[:,32:64]@Wlo, cbias ----------------
__global__ void combinew_kernel(const float* __restrict__ Woff,
                                const float* __restrict__ Wlo,
                                const float* __restrict__ blo,
                                const float* __restrict__ boff,
                                float* __restrict__ Wcomb,
                                float* __restrict__ cbias)
{
    int o = blockIdx.x;
    int c = threadIdx.x;
    float acc = 0.f;
#pragma unroll
    for (int i = 0; i < 32; i++)
        acc += Woff[o * 64 + 32 + i] * Wlo[(size_t)i * CC + c];
    Wcomb[(size_t)o * CC + c] = acc;
    if (c == 0) {
        float s2 = boff[o];
        for (int i = 0; i < 32; i++) s2 += Woff[o * 64 + 32 + i] * blo[i];
        cbias[o] = s2;
    }
}

// ---------------- offsets GEMM: off[b,96,n] = Wcomb@xgt^T + bilerp(og) + cbias ----------------
__global__ void gemmoff_kernel(const float* __restrict__ Wcomb,
                               const float* __restrict__ xgt,
                               const float* __restrict__ og,
                               const float* __restrict__ cbias,
                               float* __restrict__ off)
{
    __shared__ float As[16][96];
    __shared__ float Bs[16][64];
    int tid = threadIdx.x;
    int tx = tid & 15, ty = tid >> 4;
    int n0 = blockIdx.x * 64;
    int b  = blockIdx.y;
    const float* xb = xgt + (size_t)b * NN * CC;

    float acc[6][4];
#pragma unroll
    for (int i = 0; i < 6; i++)
#pragma unroll
        for (int j = 0; j < 4; j++) acc[i][j] = 0.f;

    for (int kb = 0; kb < CC; kb += 16) {
#pragma unroll
        for (int s = 0; s < 6; s++) {
            int idx = tid + s * 256;
            As[idx & 15][idx >> 4] = Wcomb[(size_t)(idx >> 4) * CC + kb + (idx & 15)];
        }
#pragma unroll
        for (int s = 0; s < 4; s++) {
            int idx = tid + s * 256;
            Bs[idx & 15][idx >> 4] = xb[(size_t)(n0 + (idx >> 4)) * CC + kb + (idx & 15)];
        }
        __syncthreads();
#pragma unroll
        for (int kk = 0; kk < 16; kk++) {
            float a[6], bv[4];
#pragma unroll
            for (int i = 0; i < 6; i++) a[i] = As[kk][ty * 6 + i];
#pragma unroll
            for (int j = 0; j < 4; j++) bv[j] = Bs[kk][tx * 4 + j];
#pragma unroll
            for (int i = 0; i < 6; i++)
#pragma unroll
                for (int j = 0; j < 4; j++) acc[i][j] += a[i] * bv[j];
        }
        __syncthreads();
    }

#pragma unroll
    for (int j = 0; j < 4; j++) {
        int n = n0 + tx * 4 + j;
        int y = n / WW, x = n % WW;
        float sy = fminf(fmaxf((y + 0.5f) * (7.0f / 48.0f) - 0.5f, 0.f), 6.f);
        float sx = fminf(fmaxf((x + 0.5f) * (7.0f / 48.0f) - 0.5f, 0.f), 6.f);
        int i0y = (int)floorf(sy); int i1y = min(i0y + 1, 6); float fy = sy - i0y;
        int i0x = (int)floorf(sx); int i1x = min(i0x + 1, 6); float fx = sx - i0x;
        float w00 = (1.f - fy) * (1.f - fx), w01 = (1.f - fy) * fx;
        float w10 = fy * (1.f - fx), w11 = fy * fx;
#pragma unroll
        for (int i = 0; i < 6; i++) {
            int o = ty * 6 + i;
            const float* ogp = og + ((size_t)b * 96 + o) * 49;
            float gv = w00 * ogp[i0y * 7 + i0x] + w01 * ogp[i0y * 7 + i1x]
                     + w10 * ogp[i1y * 7 + i0x] + w11 * ogp[i1y * 7 + i1x];
            off[((size_t)b * 96 + o) * NN + n] = acc[i][j] + gv + cbias[o];
        }
    }
}

// ---------------- fused deformable attention ([b,h,n,d] in, [b,n,c] out) ----------------
__global__ void attn_kernel(const float* __restrict__ qt,
                            const float* __restrict__ kt,
                            const float* __restrict__ vt,
                            const float* __restrict__ offb,
                            const float* __restrict__ abias,
                            float* __restrict__ aott)
{
    int gw   = (blockIdx.x * blockDim.x + threadIdx.x) >> 5;
    int lane = threadIdx.x & 31;
    if (gw >= BB * NHH * NN) return;
    int n = gw % NN;
    int h = (gw / NN) % NHH;
    int b = gw / (NN * NHH);
    int qx = n % WW;
    int qy = n / WW;

    size_t head = (size_t)(b * NHH + h) * NN;
    const float* kf = kt + head * HDD;
    const float* vf = vt + head * HDD;
    float qv = qt[(head + n) * HDD + lane];

    float ov = 0.f;
    if (lane < 8) ov = offb[((size_t)(b * 96 + h * 8 + lane)) * NN + n];

    float sc[NPP], vs[NPP];
#pragma unroll
    for (int p = 0; p < NPP; p++) {
        float ox = __shfl_sync(0xffffffffu, ov, 2 * p);
        float oy = __shfl_sync(0xffffffffu, ov, 2 * p + 1);
        float gx = (((float)qx + 0.5f) / (float)WW + ox / (float)WW) * 2.0f - 1.0f;
        float gy = (((float)qy + 0.5f) / (float)HH + oy / (float)HH) * 2.0f - 1.0f;
        float x = (gx + 1.0f) * 0.5f * (float)WW - 0.5f;
        float y = (gy + 1.0f) * 0.5f * (float)HH - 0.5f;
        float x0f = floorf(x), y0f = floorf(y);
        float fx = x - x0f, fy = y - y0f;
        int x0 = (int)x0f, y0 = (int)y0f;
        int x1 = x0 + 1,  y1 = y0 + 1;
        bool vx0 = (x0 >= 0 && x0 < WW), vx1 = (x1 >= 0 && x1 < WW);
        bool vy0 = (y0 >= 0 && y0 < HH), vy1 = (y1 >= 0 && y1 < HH);
        float w00 = (1.f - fx) * (1.f - fy);
        float w01 = fx * (1.f - fy);
        float w10 = (1.f - fx) * fy;
        float w11 = fx * fy;

        float ks = 0.f, vsmp = 0.f;
        if (vx0 && vy0) { size_t i = (size_t)(y0 * WW + x0) * HDD + lane; ks += w00 * kf[i]; vsmp += w00 * vf[i]; }
        if (vx1 && vy0) { size_t i = (size_t)(y0 * WW + x1) * HDD + lane; ks += w01 * kf[i]; vsmp += w01 * vf[i]; }
        if (vx0 && vy1) { size_t i = (size_t)(y1 * WW + x0) * HDD + lane; ks += w10 * kf[i]; vsmp += w10 * vf[i]; }
        if (vx1 && vy1) { size_t i = (size_t)(y1 * WW + x1) * HDD + lane; ks += w11 * kf[i]; vsmp += w11 * vf[i]; }
        vs[p] = vsmp;

        float part = qv * ks;
#pragma unroll
        for (int s = 16; s > 0; s >>= 1)
            part += __shfl_xor_sync(0xffffffffu, part, s);

        int px = (int)rintf(x); px = min(max(px, 0), WW - 1);
        int py = (int)rintf(y); py = min(max(py, 0), HH - 1);
        int bidx = abs(qy - py) * WW + abs(qx - px);
        sc[p] = part * SCALE_F + abias[h * NN + bidx];
    }

    float m = fmaxf(fmaxf(sc[0], sc[1]), fmaxf(sc[2], sc[3]));
    float e0 = expf(sc[0] - m), e1 = expf(sc[1] - m),
          e2 = expf(sc[2] - m), e3 = expf(sc[3] - m);
    float denom = e0 + e1 + e2 + e3;
    float o = (e0 * vs[0] + e1 * vs[1] + e2 * vs[2] + e3 * vs[3]) / denom;
    aott[((size_t)b * NN + n) * CC + h * HDD + lane] = o;
}

// ---------------- launch ----------------
extern "C" void kernel_launch(void* const* d_in, const int* in_sizes, int n_in,
                              void* d_out, int out_size)
{
    const float* local_feat    = (const float*)d_in[0];
    const float* context_prior = (const float*)d_in[1];
    const float* deformable_x  = (const float*)d_in[2];
    const float* W_q   = (const float*)d_in[3];
    const float* W_k   = (const float*)d_in[4];
    const float* W_v   = (const float*)d_in[5];
    const float* W_pre = (const float*)d_in[6];
    const float* ln1_g = (const float*)d_in[7];
    const float* ln1_b = (const float*)d_in[8];
    const float* W_post= (const float*)d_in[9];
    const float* dw_w  = (const float*)d_in[10];
    const float* dw_b  = (const float*)d_in[11];
    const float* ln2_g = (const float*)d_in[12];
    const float* ln2_b = (const float*)d_in[13];
    const float* W_lo  = (const float*)d_in[14];
    const float* b_lo  = (const float*)d_in[15];
    const float* W_off = (const float*)d_in[16];
    const float* b_off = (const float*)d_in[17];
    const float* abias = (const float*)d_in[18];
    const float* W_p   = (const float*)d_in[19];
    const float* bn_g  = (const float*)d_in[20];
    const float* bn_b  = (const float*)d_in[21];
    const float* bn_m  = (const float*)d_in[22];
    const float* bn_v  = (const float*)d_in[23];
    float* out = (float*)d_out;

    float *cg, *qt, *kt, *vt, *aot, *dw, *dwt, *xgt;
    float *off, *pool, *og, *Wcomb, *cbias;
    __nv_bfloat16 *wh, *wl, *bh, *bl;
    cudaGetSymbolAddress((void**)&cg,    g_cg);
    cudaGetSymbolAddress((void**)&qt,    g_qt);
    cudaGetSymbolAddress((void**)&kt,    g_kt);
    cudaGetSymbolAddress((void**)&vt,    g_vt);
    cudaGetSymbolAddress((void**)&aot,   g_aot);
    cudaGetSymbolAddress((void**)&dw,    g_dw);
    cudaGetSymbolAddress((void**)&dwt,   g_dwt);
    cudaGetSymbolAddress((void**)&xgt,   g_xgt);
    cudaGetSymbolAddress((void**)&off,   g_off);
    cudaGetSymbolAddress((void**)&pool,  g_pool);
    cudaGetSymbolAddress((void**)&og,    g_og);
    cudaGetSymbolAddress((void**)&Wcomb, g_Wcomb);
    cudaGetSymbolAddress((void**)&cbias, g_cbias);
    cudaGetSymbolAddress((void**)&wh,    g_wh);
    cudaGetSymbolAddress((void**)&wl,    g_wl);
    cudaGetSymbolAddress((void**)&bh,    g_bh);
    cudaGetSymbolAddress((void**)&bl,    g_bl);

    const int WSZ = CC * CC;                    // 147456
    const int WGRID = WSZ / 1024;               // 144
    const int EGRID = BB * NN * CC / 1024;      // 6912
    dim3 gb(NN / 128, CC / 128, BB);            // (18, 3, 8)
    dim3 gt(NN / 32, CC / 64, BB);              // (72, 6, 8)

    // weights -> bf16 hi/lo (slices 0:q 1:k 2:v 3:pre 4:p)
    conv_hilo<<<WGRID, 256>>>(W_q,   wh + 0 * WSZ, wl + 0 * WSZ);
    conv_hilo<<<WGRID, 256>>>(W_k,   wh + 1 * WSZ, wl + 1 * WSZ);
    conv_hilo<<<WGRID, 256>>>(W_v,   wh + 2 * WSZ, wl + 2 * WSZ);
    conv_hilo<<<WGRID, 256>>>(W_pre, wh + 3 * WSZ, wl + 3 * WSZ);
    conv_hilo<<<WGRID, 256>>>(W_p,   wh + 4 * WSZ, wl + 4 * WSZ);

    // q = W_q @ local_feat  -> [b,h,n,d]
    convbt_kernel<<<gt, 256>>>(local_feat, bh, bl);
    gemm_mma<<<gb, 256, SMEM_DYN>>>(wh + 0 * WSZ, wl + 0 * WSZ, bh, bl, qt, 1, 0,
                                    nullptr, nullptr, nullptr, nullptr);

    // k, cg from context_prior
    convbt_kernel<<<gt, 256>>>(context_prior, bh, bl);
    gemm_mma<<<gb, 256, SMEM_DYN>>>(wh + 1 * WSZ, wl + 1 * WSZ, bh, bl, kt, 1, 0,
                                    nullptr, nullptr, nullptr, nullptr);
    gemm_mma<<<gb, 256, SMEM_DYN>>>(wh + 3 * WSZ, wl + 3 * WSZ, bh, bl, cg, 0, 1,
                                    nullptr, nullptr, nullptr, nullptr);

    // v from deformable_x
    convbt_kernel<<<gt, 256>>>(deformable_x, bh, bl);
    gemm_mma<<<gb, 256, SMEM_DYN>>>(wh + 2 * WSZ, wl + 2 * WSZ, bh, bl, vt, 1, 0,
                                    nullptr, nullptr, nullptr, nullptr);

    // guide path
    pool_kernel<<<(BB * CC * 49 + 255) / 256, 256>>>(cg, pool);
    ln1_post_og_kernel<<<BB * 49, CC>>>(pool, ln1_g, ln1_b, W_post, W_off, og);

    // offsets path
    dwconv_kernel<<<(BB * CC * NN + 255) / 256, 256>>>(local_feat, dw_w, dw_b, dw);
    dim3 td(NN / 32, CC / 32, BB);
    transpose_kernel<<<td, 256>>>(dw, dwt, CC, NN);
    ln2gelu_kernel<<<(BB * NN) / 8, 256>>>(dwt, ln2_g, ln2_b, xgt);
    combinew_kernel<<<96, CC>>>(W_off, W_lo, b_lo, b_off, Wcomb, cbias);
    dim3 go(NN / 64, BB);
    gemmoff_kernel<<<go, 256>>>(Wcomb, xgt, og, cbias, off);

    // attention -> aot [b][n][c]
    attn_kernel<<<(BB * NHH * NN) / 8, 256>>>(qt, kt, vt, off, abias, aot);

    // final projection + BN
    conv_hilo<<<EGRID, 256>>>(aot, bh, bl);
    gemm_mma<<<gb, 256, SMEM_DYN>>>(wh + 4 * WSZ, wl + 4 * WSZ, bh, bl, out, 0, 2,
                                    bn_g, bn_b, bn_m, bn_v);
}